// round 1
// baseline (speedup 1.0000x reference)
#include <cuda_runtime.h>

#define B_DIM 64
#define M_DIM 2048
#define H_DIM 512
#define NTOK (B_DIM * M_DIM)
#define THRESH 0.99f

// Scratch (allocation-free rule: __device__ globals)
__device__ int g_cont[NTOK];
__device__ int g_pos[NTOK];

// K1: one warp per token. Computes p = sigmoid(h.W + b), exit mask,
// update u, writes weights_new = h*u + w*(1-u) into out[0], stores cont flag.
__global__ void __launch_bounds__(256)
k1_prob_weights(const float* __restrict__ h,
                const float* __restrict__ W,
                const float* __restrict__ bias,
                const float* __restrict__ acc_p,
                const float* __restrict__ weights,
                float* __restrict__ out0)
{
    __shared__ float4 sW[H_DIM / 4];
    const int tid = threadIdx.x;
    const float4* W4 = (const float4*)W;
    for (int i = tid; i < H_DIM / 4; i += 256) sW[i] = W4[i];
    __syncthreads();

    const int tok  = blockIdx.x * 8 + (tid >> 5);
    const int lane = tid & 31;

    const float4* hp = (const float4*)(h + (size_t)tok * H_DIM);
    float4 hv[4];
    float sum = 0.f;
#pragma unroll
    for (int j = 0; j < 4; j++) {
        float4 a = hp[j * 32 + lane];
        float4 w = sW[j * 32 + lane];
        hv[j] = a;
        sum += a.x * w.x + a.y * w.y + a.z * w.z + a.w * w.w;
    }
#pragma unroll
    for (int s = 16; s; s >>= 1) sum += __shfl_xor_sync(0xffffffffu, sum, s);

    const float p  = 1.f / (1.f + expf(-(sum + bias[0])));
    const float ap = acc_p[tok];
    const int   ex = ((ap + p) >= THRESH) ? 1 : 0;
    const float u  = ex ? (1.f - p) : p;
    const float om = 1.f - u;

    const float4* wp = (const float4*)(weights + (size_t)tok * H_DIM);
    float4*       o  = (float4*)(out0 + (size_t)tok * H_DIM);
#pragma unroll
    for (int j = 0; j < 4; j++) {
        float4 w = wp[j * 32 + lane];
        float4 a = hv[j];
        float4 r;
        r.x = a.x * u + w.x * om;
        r.y = a.y * u + w.y * om;
        r.z = a.z * u + w.z * om;
        r.w = a.w * u + w.w * om;
        o[j * 32 + lane] = r;
    }
    if (lane == 0) g_cont[tok] = ex ^ 1;
}

// K2: one block per row. Inclusive Hillis-Steele scan of cont flags over M,
// then emit scatter position: continuing -> excl; halted -> Ctot + (m - excl).
__global__ void __launch_bounds__(1024)
k2_scan()
{
    __shared__ int sa[M_DIM];
    __shared__ int sb[M_DIM];
    const int row = blockIdx.x;
    const int tid = threadIdx.x;
    const int* cont = g_cont + (size_t)row * M_DIM;

    for (int i = tid; i < M_DIM; i += 1024) sa[i] = cont[i];
    __syncthreads();

    int* src = sa;
    int* dst = sb;
    for (int off = 1; off < M_DIM; off <<= 1) {
        for (int i = tid; i < M_DIM; i += 1024) {
            int v = src[i];
            if (i >= off) v += src[i - off];
            dst[i] = v;
        }
        __syncthreads();
        int* t = src; src = dst; dst = t;
    }

    const int ctot = src[M_DIM - 1];
    for (int i = tid; i < M_DIM; i += 1024) {
        int c    = cont[i];
        int excl = src[i] - c;
        g_pos[(size_t)row * M_DIM + i] = c ? excl : (ctot + (i - excl));
    }
}

// K3: one warp per token. Scatter h row (continuing) or zeros (halted) to
// out[1] at the compacted position. Every slot written exactly once.
__global__ void __launch_bounds__(256)
k3_compact(const float* __restrict__ h, float* __restrict__ out1)
{
    const int tok  = blockIdx.x * 8 + (threadIdx.x >> 5);
    const int lane = threadIdx.x & 31;
    const int c    = g_cont[tok];
    const int pos  = g_pos[tok];
    const int row  = tok >> 11;  // tok / M_DIM

    float4* dst = (float4*)(out1 + ((size_t)(row * M_DIM + pos)) * H_DIM);
    if (c) {
        const float4* src = (const float4*)(h + (size_t)tok * H_DIM);
#pragma unroll
        for (int j = 0; j < 4; j++) dst[j * 32 + lane] = src[j * 32 + lane];
    } else {
        const float4 z = make_float4(0.f, 0.f, 0.f, 0.f);
#pragma unroll
        for (int j = 0; j < 4; j++) dst[j * 32 + lane] = z;
    }
}

extern "C" void kernel_launch(void* const* d_in, const int* in_sizes, int n_in,
                              void* d_out, int out_size)
{
    // metadata order: h, W, b, acc_p, remainders, weights
    const float* h       = (const float*)d_in[0];
    const float* W       = (const float*)d_in[1];
    const float* bias    = (const float*)d_in[2];
    const float* acc_p   = (const float*)d_in[3];
    // d_in[4] = remainders: not needed for outputs
    const float* weights = (const float*)d_in[5];

    float* out0 = (float*)d_out;
    float* out1 = out0 + (size_t)B_DIM * M_DIM * H_DIM;

    k1_prob_weights<<<NTOK / 8, 256>>>(h, W, bias, acc_p, weights, out0);
    k2_scan<<<B_DIM, 1024>>>();
    k3_compact<<<NTOK / 8, 256>>>(h, out1);
}

// round 2
// speedup vs baseline: 1.1721x; 1.1721x over previous
#include <cuda_runtime.h>

#define B_DIM 64
#define M_DIM 2048
#define H_DIM 512
#define NTOK (B_DIM * M_DIM)
#define THRESH 0.99f

#define TPB 32                       // tokens per block (one warp per token)
#define BLK_PER_ROW (M_DIM / TPB)    // 64
#define NBLK (B_DIM * BLK_PER_ROW)   // 4096

// Decoupled-lookback state: per block, packed (count << 2) | status.
// status: 0 = invalid, 1 = aggregate available, 2 = inclusive prefix available.
__device__ unsigned long long g_state[NBLK];
__device__ int g_ctot[B_DIM];

__global__ void k0_init()
{
    int i = blockIdx.x * blockDim.x + threadIdx.x;
    if (i < NBLK) g_state[i] = 0ull;
}

// Fused kernel: dot(h,W) -> p -> flags; publish aggregate; write out0;
// lookback for row-exclusive prefix; scatter continuing h rows (still in
// registers) to their compacted slots in out1.
__global__ void __launch_bounds__(1024, 1)
k1_fused(const float* __restrict__ h,
         const float* __restrict__ W,
         const float* __restrict__ bias,
         const float* __restrict__ acc_p,
         const float* __restrict__ weights,
         float* __restrict__ out0,
         float* __restrict__ out1)
{
    __shared__ float4 sW[H_DIM / 4];
    __shared__ int scont[TPB];
    __shared__ int s_excl;

    const int tid  = threadIdx.x;
    const int warp = tid >> 5;
    const int lane = tid & 31;
    const int row  = blockIdx.x / BLK_PER_ROW;
    const int cb   = blockIdx.x % BLK_PER_ROW;      // chunk index within row
    const int tok  = row * M_DIM + cb * TPB + warp; // this warp's token

    const float4* W4 = (const float4*)W;
    for (int i = tid; i < H_DIM / 4; i += 1024) sW[i] = W4[i];
    __syncthreads();

    // --- load h row (kept in registers), dot with W ---
    const float4* hp = (const float4*)(h + (size_t)tok * H_DIM);
    float4 hv[4];
    float sum = 0.f;
#pragma unroll
    for (int j = 0; j < 4; j++) {
        float4 a = hp[j * 32 + lane];
        float4 w = sW[j * 32 + lane];
        hv[j] = a;
        sum += a.x * w.x + a.y * w.y + a.z * w.z + a.w * w.w;
    }
#pragma unroll
    for (int s = 16; s; s >>= 1) sum += __shfl_xor_sync(0xffffffffu, sum, s);

    const float p    = 1.f / (1.f + expf(-(sum + bias[0])));
    const int   ex   = ((acc_p[tok] + p) >= THRESH) ? 1 : 0;
    const int   cont = ex ^ 1;
    const float u    = ex ? (1.f - p) : p;
    const float om   = 1.f - u;

    // --- block-local flags -> ballot word (every thread gets same word) ---
    if (lane == 0) scont[warp] = cont;
    __syncthreads();
    const unsigned flags = __ballot_sync(0xffffffffu, scont[lane] != 0);
    const int block_agg  = __popc(flags);
    const int local_excl = __popc(flags & ((1u << warp) - 1));

    // --- publish aggregate/prefix EARLY (off the critical chain) ---
    if (tid == 0) {
        unsigned long long pub = ((unsigned long long)block_agg << 2)
                               | (cb == 0 ? 2ull : 1ull);
        atomicExch(&g_state[blockIdx.x], pub);
        if (cb == 0) s_excl = 0;
    }

    // --- write out0 = h*u + weights*(1-u) (overlaps lookback latency) ---
    const float4* wp = (const float4*)(weights + (size_t)tok * H_DIM);
    float4*       o0 = (float4*)(out0 + (size_t)tok * H_DIM);
#pragma unroll
    for (int j = 0; j < 4; j++) {
        float4 w = wp[j * 32 + lane];
        float4 a = hv[j];
        float4 r;
        r.x = a.x * u + w.x * om;
        r.y = a.y * u + w.y * om;
        r.z = a.z * u + w.z * om;
        r.w = a.w * u + w.w * om;
        o0[j * 32 + lane] = r;
    }

    // --- warp-parallel decoupled lookback (warp 0) ---
    if (warp == 0 && cb > 0) {
        int excl = 0;
        int k = cb - 1;
        for (;;) {
            int idx = k - lane;     // lane 0 = nearest predecessor
            unsigned long long v = 0;
            if (idx >= 0) {
                const volatile unsigned long long* sp =
                    (const volatile unsigned long long*)&g_state[row * BLK_PER_ROW + idx];
                do { v = *sp; } while ((v & 3ull) == 0ull);
            }
            unsigned pmask = __ballot_sync(0xffffffffu,
                                           (idx >= 0) && ((v & 3ull) == 2ull));
            int firstP  = pmask ? (__ffs(pmask) - 1) : 32;
            int contrib = ((idx >= 0) && (lane <= firstP)) ? (int)(v >> 2) : 0;
#pragma unroll
            for (int s = 16; s; s >>= 1)
                contrib += __shfl_xor_sync(0xffffffffu, contrib, s);
            excl += contrib;
            if (firstP != 32) break;   // hit an inclusive-prefix entry
            k -= 32;                   // whole window was aggregates; go back
        }
        if (lane == 0) {
            atomicExch(&g_state[blockIdx.x],
                       ((unsigned long long)(excl + block_agg) << 2) | 2ull);
            if (cb == BLK_PER_ROW - 1) g_ctot[row] = excl + block_agg;
            s_excl = excl;
        }
    }
    if (cb == 0 && cb == BLK_PER_ROW - 1 && tid == 0) g_ctot[row] = block_agg;
    __syncthreads();

    // --- scatter continuing tokens to compacted slots (h from registers) ---
    if (cont) {
        const int dst = s_excl + local_excl;
        float4* o1 = (float4*)(out1 + ((size_t)row * M_DIM + dst) * H_DIM);
#pragma unroll
        for (int j = 0; j < 4; j++) o1[j * 32 + lane] = hv[j];
    }
}

// Tail zero-fill: halted region of each row is slots [ctot, M) -> zeros.
__global__ void __launch_bounds__(1024)
k2_tailzero(float* __restrict__ out1)
{
    const int row  = blockIdx.x;
    const int ctot = g_ctot[row];
    float4* o = (float4*)(out1 + (size_t)row * M_DIM * H_DIM);
    const int start4 = ctot * (H_DIM / 4);
    const int end4   = M_DIM * (H_DIM / 4);
    const float4 z = make_float4(0.f, 0.f, 0.f, 0.f);
    for (int i = start4 + threadIdx.x; i < end4; i += 1024) o[i] = z;
}

extern "C" void kernel_launch(void* const* d_in, const int* in_sizes, int n_in,
                              void* d_out, int out_size)
{
    // metadata order: h, W, b, acc_p, remainders, weights
    const float* h       = (const float*)d_in[0];
    const float* W       = (const float*)d_in[1];
    const float* bias    = (const float*)d_in[2];
    const float* acc_p   = (const float*)d_in[3];
    const float* weights = (const float*)d_in[5];

    float* out0 = (float*)d_out;
    float* out1 = out0 + (size_t)B_DIM * M_DIM * H_DIM;

    k0_init<<<NBLK / 1024, 1024>>>();
    k1_fused<<<NBLK, 1024>>>(h, W, bias, acc_p, weights, out0, out1);
    k2_tailzero<<<B_DIM, 1024>>>(out1);
}